// round 7
// baseline (speedup 1.0000x reference)
#include <cuda_runtime.h>
#include <cuda_bf16.h>
#include <math.h>
#include <cstdint>

#define L      40
#define BATCH  128
#define HIDI   512
#define H      512
#define G4     2048
#define NCLS   7000
#define NPAD   7040
#define HW     256
#define M5     (L*BATCH)   /* 5120 */
#define KCAT   1024

// ---------------- scratch (static device globals: no allocation) ----------------
__device__ float g_xg [M5*G4];
__device__ float g_hem[M5*H];
__device__ float g_fatt[M5*HW];
__device__ float g_logits[(size_t)M5*NCLS];
__device__ __nv_bfloat16 g_xtsbf[M5*HIDI];
__device__ __nv_bfloat16 g_catbf[(size_t)M5*KCAT];   // h | att, bf16
__device__ __nv_bfloat16 g_linbf[(size_t)NPAD*KCAT];
__device__ __nv_bfloat16 g_whhbf[G4*H];
__device__ __nv_bfloat16 g_wihbf[G4*HIDI];
__device__ __nv_bfloat16 g_hemwbf[H*H];
__device__ unsigned int g_bar_cnt;
__device__ volatile unsigned int g_bar_gen;

__device__ __forceinline__ float tanh_approx(float x) {
    float y; asm("tanh.approx.f32 %0, %1;" : "=f"(y) : "f"(x)); return y;
}
__device__ __forceinline__ float sigmoid_acc(float x) { return 1.0f / (1.0f + expf(-x)); }

__device__ __forceinline__ uint32_t smem_u32(const void* p) {
    uint32_t a;
    asm("{ .reg .u64 t; cvta.to.shared.u64 t, %1; cvt.u32.u64 %0, t; }" : "=r"(a) : "l"(p));
    return a;
}
__device__ __forceinline__ void ldsm_x4(uint32_t* r, uint32_t addr) {
    asm volatile("ldmatrix.sync.aligned.m8n8.x4.shared.b16 {%0,%1,%2,%3}, [%4];"
                 : "=r"(r[0]), "=r"(r[1]), "=r"(r[2]), "=r"(r[3]) : "r"(addr));
}
__device__ __forceinline__ void ldsm_x2(uint32_t* r, uint32_t addr) {
    asm volatile("ldmatrix.sync.aligned.m8n8.x2.shared.b16 {%0,%1}, [%2];"
                 : "=r"(r[0]), "=r"(r[1]) : "r"(addr));
}
__device__ __forceinline__ void mma16816(float* c, const uint32_t* a, uint32_t b0, uint32_t b1) {
    asm volatile("mma.sync.aligned.m16n8k16.row.col.f32.bf16.bf16.f32 "
                 "{%0,%1,%2,%3}, {%4,%5,%6,%7}, {%8,%9}, {%0,%1,%2,%3};"
                 : "+f"(c[0]), "+f"(c[1]), "+f"(c[2]), "+f"(c[3])
                 : "r"(a[0]), "r"(a[1]), "r"(a[2]), "r"(a[3]), "r"(b0), "r"(b1));
}

// grid-wide software barrier (all CTAs co-resident; count self-resets)
__device__ __forceinline__ void gbar(int nblk) {
    __syncthreads();
    if (threadIdx.x == 0) {
        __threadfence();
        unsigned int gen = g_bar_gen;
        if (atomicAdd(&g_bar_cnt, 1u) == (unsigned)(nblk - 1)) {
            g_bar_cnt = 0;
            __threadfence();
            g_bar_gen = gen + 1;
        } else {
            while (g_bar_gen == gen) { __nanosleep(32); }
        }
        __threadfence();
    }
    __syncthreads();
}

// ---------------- K0: gather teacher-forced inputs (bf16 out) ----------------
__global__ void gather_kernel(const float* __restrict__ hidden_en,
                              const float* __restrict__ embed_w,
                              const int*   __restrict__ target) {
    const int m = blockIdx.x;
    const int l = m / BATCH, b = m % BATCH;
    const int k = threadIdx.x * 4;
    const float* src = (l == 0)
        ? (hidden_en + (size_t)b * HIDI)
        : (embed_w   + (size_t)target[b * L + (l - 1)] * HIDI);
    float4 v = *(const float4*)&src[k];
    __nv_bfloat162 a = __floats2bfloat162_rn(v.x, v.y);
    __nv_bfloat162 c = __floats2bfloat162_rn(v.z, v.w);
    *(uint2*)&g_xtsbf[(size_t)m * HIDI + k] = make_uint2(*(uint32_t*)&a, *(uint32_t*)&c);
}

// ---------------- generic bf16 HMMA GEMM (K1, K3, K5) ----------------
#define HG_LDS   40
#define HG_ROWB  80
#define HG_BUFB  (128*HG_ROWB)

__global__ void __launch_bounds__(256) hgemm_nt_bias(
        const __nv_bfloat16* __restrict__ A, int lda,
        const __nv_bfloat16* __restrict__ B, int ldb,
        const float* __restrict__ bias,
        float* __restrict__ C, int ldc,
        int nlim, int K) {
    __shared__ __nv_bfloat16 sA[2][128][HG_LDS];
    __shared__ __nv_bfloat16 sB[2][128][HG_LDS];
    const int tid  = threadIdx.x;
    const int w    = tid >> 5, lane = tid & 31;
    const int wm   = w >> 2, wn = w & 3;
    const int bm   = blockIdx.y * 128;
    const int bn   = blockIdx.x * 128;
    const int nch  = K >> 5;

    const uint32_t uA = smem_u32(&sA[0][0][0]);
    const uint32_t uB = smem_u32(&sB[0][0][0]);

    const int gr0 = tid >> 1;
    const int gs0 = tid & 1;
    const int gs1 = 2 + (tid & 1);
    const __nv_bfloat16* arow = A + (size_t)(bm + gr0) * lda;
    const __nv_bfloat16* brow = B + (size_t)(bn + gr0) * ldb;

    float acc[4][4][4];
#pragma unroll
    for (int i = 0; i < 4; i++)
#pragma unroll
        for (int j = 0; j < 4; j++)
#pragma unroll
            for (int q = 0; q < 4; q++) acc[i][j][q] = 0.0f;

    uint4 ra[2], rb[2];
    ra[0] = *(const uint4*)(arow + gs0*8);
    ra[1] = *(const uint4*)(arow + gs1*8);
    rb[0] = *(const uint4*)(brow + gs0*8);
    rb[1] = *(const uint4*)(brow + gs1*8);
    *(uint4*)((char*)&sA[0][0][0] + gr0*HG_ROWB + gs0*16) = ra[0];
    *(uint4*)((char*)&sA[0][0][0] + gr0*HG_ROWB + gs1*16) = ra[1];
    *(uint4*)((char*)&sB[0][0][0] + gr0*HG_ROWB + gs0*16) = rb[0];
    *(uint4*)((char*)&sB[0][0][0] + gr0*HG_ROWB + gs1*16) = rb[1];

    const uint32_t aoff = (uint32_t)(wm*64 + (lane & 15)) * HG_ROWB + (uint32_t)(lane >> 4) * 16;
    const uint32_t boff = (uint32_t)(wn*32 + (lane & 15)) * HG_ROWB + (uint32_t)(lane >> 4) * 16;

    for (int c = 0; c < nch; c++) {
        __syncthreads();
        if (c + 1 < nch) {
            const int k0 = (c + 1) * 32;
            ra[0] = *(const uint4*)(arow + k0 + gs0*8);
            ra[1] = *(const uint4*)(arow + k0 + gs1*8);
            rb[0] = *(const uint4*)(brow + k0 + gs0*8);
            rb[1] = *(const uint4*)(brow + k0 + gs1*8);
        }
        const uint32_t bufA = uA + (c & 1) * HG_BUFB;
        const uint32_t bufB = uB + (c & 1) * HG_BUFB;
#pragma unroll
        for (int ka = 0; ka < 2; ka++) {
            uint32_t af[4][4];
            uint32_t bf[2][4];
#pragma unroll
            for (int ma = 0; ma < 4; ma++)
                ldsm_x4(af[ma], bufA + aoff + ma*16*HG_ROWB + ka*32);
#pragma unroll
            for (int ng = 0; ng < 2; ng++)
                ldsm_x4(bf[ng], bufB + boff + ng*16*HG_ROWB + ka*32);
#pragma unroll
            for (int ma = 0; ma < 4; ma++)
#pragma unroll
                for (int ng = 0; ng < 2; ng++) {
                    mma16816(acc[ma][ng*2+0], af[ma], bf[ng][0], bf[ng][2]);
                    mma16816(acc[ma][ng*2+1], af[ma], bf[ng][1], bf[ng][3]);
                }
        }
        if (c + 1 < nch) {
            __syncthreads();
            char* dA = (char*)&sA[(c+1)&1][0][0];
            char* dB = (char*)&sB[(c+1)&1][0][0];
            *(uint4*)(dA + gr0*HG_ROWB + gs0*16) = ra[0];
            *(uint4*)(dA + gr0*HG_ROWB + gs1*16) = ra[1];
            *(uint4*)(dB + gr0*HG_ROWB + gs0*16) = rb[0];
            *(uint4*)(dB + gr0*HG_ROWB + gs1*16) = rb[1];
        }
    }

    const int g = lane >> 2, t = lane & 3;
#pragma unroll
    for (int ma = 0; ma < 4; ma++) {
        const int r0 = bm + wm*64 + ma*16 + g;
#pragma unroll
        for (int na = 0; na < 4; na++) {
            const int col = bn + wn*32 + na*8 + t*2;
            if (col + 1 < nlim) {
                const float2 bv = *(const float2*)&bias[col];
                *(float2*)&C[(size_t)r0 * ldc + col] =
                    make_float2(acc[ma][na][0] + bv.x, acc[ma][na][1] + bv.y);
                *(float2*)&C[(size_t)(r0 + 8) * ldc + col] =
                    make_float2(acc[ma][na][2] + bv.x, acc[ma][na][3] + bv.y);
            }
        }
    }
}

// ---------------- persistent LSTM: gate-sliced, 1 barrier/step ----------------
// 64 CTAs x 256 thr. CTA owns d-slice dj=bid*8 for ALL 4 gates (W rows
// {g*512+dj..+8}). W slice (16 chunks x 32 rows x 80B) + c-state resident in
// SMEM. Per step: stream h in 16 k-chunks (double buffered) -> HMMA ->
// CTA-local pointwise -> write h (bf16) -> ONE gbar.
#define LP_NBLK 64
#define LP_SM_W     0
#define LP_SM_H     40960
#define LP_SM_G     61440
#define LP_SM_C     77824
#define LP_SM_BH    81920
#define LP_SM_TOT   82048

__global__ void __launch_bounds__(256) lstm_persist(const float* __restrict__ b_hh) {
    extern __shared__ char sm[];
    __nv_bfloat16* sW = (__nv_bfloat16*)(sm + LP_SM_W);
    float* sg  = (float*)(sm + LP_SM_G);    // [4 gates][128 b][8 d]
    float* sc  = (float*)(sm + LP_SM_C);    // [128 b][8 d]
    float* sbh = (float*)(sm + LP_SM_BH);   // [4][8]
    const int tid = threadIdx.x;
    const int w = tid >> 5, lane = tid & 31;
    const int wm = w >> 2, wn = w & 3;
    const int bid = blockIdx.x;
    const int dj = bid * 8;
    const uint32_t uW = smem_u32(sm + LP_SM_W);
    const uint32_t uH = smem_u32(sm + LP_SM_H);

    // resident W slice: 16 chunks x 32 rows x 64B (padded 80B rows)
    for (int i = tid; i < 2048; i += 256) {
        const int ka = i >> 7, rem = i & 127, r = rem >> 2, u = rem & 3;
        const int g = r >> 3, r8 = r & 7;
        *(uint4*)(sm + LP_SM_W + ka*2560 + r*80 + u*16) =
            *(const uint4*)(g_whhbf + (size_t)(g*512 + dj + r8)*512 + ka*32 + u*8);
    }
    if (tid < 32) sbh[tid] = b_hh[(tid >> 3)*512 + dj + (tid & 7)];
    for (int i = tid; i < 1024; i += 256) sc[i] = 0.0f;
    __syncthreads();

    const uint32_t aoffr = (uint32_t)(wm*64 + (lane & 15))*80 + (uint32_t)(lane >> 4)*16;
    const uint32_t brow_l = (uint32_t)(wn*8 + (lane & 7))*80 + (uint32_t)((lane >> 3) & 1)*16;
    const int g8 = lane >> 2, t4 = lane & 3;
    const int hr = tid >> 1, ho = (tid & 1)*32;

    for (int l = 0; l < L; l++) {
        if (l > 0) {
            uint4 h0, h1;
            {
                const char* src = (const char*)(g_catbf + (size_t)((l-1)*BATCH + hr)*KCAT) + ho;
                h0 = *(const uint4*)src; h1 = *(const uint4*)(src + 16);
            }
            float acc[4][4];
#pragma unroll
            for (int ma = 0; ma < 4; ma++)
#pragma unroll
                for (int q = 0; q < 4; q++) acc[ma][q] = 0.0f;

            for (int ka = 0; ka < 16; ka++) {
                __syncthreads();
                {
                    char* dst = sm + LP_SM_H + (ka & 1)*10240 + hr*80 + ho;
                    *(uint4*)dst = h0; *(uint4*)(dst + 16) = h1;
                }
                __syncthreads();
                if (ka + 1 < 16) {
                    const char* src = (const char*)(g_catbf + (size_t)((l-1)*BATCH + hr)*KCAT + (ka+1)*32) + ho;
                    h0 = *(const uint4*)src; h1 = *(const uint4*)(src + 16);
                }
                const uint32_t bufA = uH + (ka & 1)*10240;
                const uint32_t wch  = uW + ka*2560 + brow_l;
#pragma unroll
                for (int ks = 0; ks < 2; ks++) {
                    uint32_t bfr[2];
                    ldsm_x2(bfr, wch + ks*32);
#pragma unroll
                    for (int ma = 0; ma < 4; ma++) {
                        uint32_t af[4];
                        ldsm_x4(af, bufA + aoffr + ma*16*80 + ks*32);
                        mma16816(acc[ma], af, bfr[0], bfr[1]);
                    }
                }
            }
            // stage gate pre-activations in smem
#pragma unroll
            for (int ma = 0; ma < 4; ma++) {
                const int r0 = wm*64 + ma*16 + g8;
                *(float2*)&sg[((wn*128 + r0)    )*8 + t4*2] = make_float2(acc[ma][0], acc[ma][1]);
                *(float2*)&sg[((wn*128 + r0 + 8))*8 + t4*2] = make_float2(acc[ma][2], acc[ma][3]);
            }
            __syncthreads();
        }
        // CTA-local pointwise: thread -> (b = tid>>1, d = dq..dq+4)
        {
            const int b = tid >> 1, dq = (tid & 1)*4;
            float gv[4][4];
#pragma unroll
            for (int g = 0; g < 4; g++) {
                float4 xv = *(const float4*)&g_xg[(size_t)(l*BATCH + b)*G4 + g*512 + dj + dq];
                gv[g][0] = xv.x + sbh[g*8 + dq + 0];
                gv[g][1] = xv.y + sbh[g*8 + dq + 1];
                gv[g][2] = xv.z + sbh[g*8 + dq + 2];
                gv[g][3] = xv.w + sbh[g*8 + dq + 3];
                if (l > 0) {
#pragma unroll
                    for (int j = 0; j < 4; j++) gv[g][j] += sg[(g*128 + b)*8 + dq + j];
                }
            }
            __nv_bfloat16 hb[4];
#pragma unroll
            for (int j = 0; j < 4; j++) {
                float ig = sigmoid_acc(gv[0][j]);
                float fg = sigmoid_acc(gv[1][j]);
                float gg = tanhf(gv[2][j]);
                float og = sigmoid_acc(gv[3][j]);
                float cp = sc[b*8 + dq + j];
                float cn = fg*cp + ig*gg;
                sc[b*8 + dq + j] = cn;
                hb[j] = __float2bfloat16(og * tanhf(cn));
            }
            *(uint2*)&g_catbf[(size_t)(l*BATCH + b)*KCAT + dj + dq] = *(uint2*)hb;
        }
        gbar(LP_NBLK);
    }
}

// ---------------- K4a ----------------
__global__ void featatt_kernel(const float* __restrict__ x_em,
                               const float* __restrict__ attw_w,
                               const float* __restrict__ attw_b) {
    __shared__ float sx[512][17];
    __shared__ float sh_hem[512];
    __shared__ float sh_w[512];
    __shared__ float red[16][17];
    const int tid = threadIdx.x;
    const int b  = blockIdx.y;
    const int n0 = blockIdx.x * 16;
#pragma unroll
    for (int i = 0; i < 32; i++) {
        int e = tid + i*256;
        int c = e >> 4, j = e & 15;
        sx[c][j] = x_em[((size_t)b*512 + c) * 256 + n0 + j];
    }
    sh_w[tid]     = attw_w[tid];
    sh_w[tid+256] = attw_w[tid+256];
    const float ab = attw_b[0];
    const int j  = tid % 16;
    const int cg = tid / 16;
    for (int l = 0; l < L; l++) {
        __syncthreads();
        sh_hem[tid]     = g_hem[(size_t)(l*BATCH + b) * H + tid];
        sh_hem[tid+256] = g_hem[(size_t)(l*BATCH + b) * H + tid + 256];
        __syncthreads();
        float acc = 0.0f;
#pragma unroll 8
        for (int i = 0; i < 32; i++) {
            int c = cg*32 + i;
            acc += tanh_approx(sx[c][j] + sh_hem[c]) * sh_w[c];
        }
        red[cg][j] = acc;
        __syncthreads();
        if (tid < 16) {
            float s = 0.0f;
#pragma unroll
            for (int i = 0; i < 16; i++) s += red[i][tid];
            g_fatt[(size_t)(l*BATCH + b) * HW + n0 + tid] = s + ab;
        }
    }
}

// ---------------- K4b ----------------
__global__ void attred_kernel(const float* __restrict__ att_x_em) {
    __shared__ float s_alpha[L][HW];
    __shared__ float s_red[8];
    __shared__ float s_val;
    const int tid = threadIdx.x;
    const int b = blockIdx.x;
    const int lane = tid & 31, wid = tid >> 5;
    for (int l = 0; l < L; l++) {
        float v = g_fatt[(size_t)(l*BATCH + b) * HW + tid];
        float m = v;
#pragma unroll
        for (int o = 16; o > 0; o >>= 1) m = fmaxf(m, __shfl_xor_sync(~0u, m, o));
        if (lane == 0) s_red[wid] = m;
        __syncthreads();
        if (tid == 0) {
            float mm = s_red[0];
#pragma unroll
            for (int i = 1; i < 8; i++) mm = fmaxf(mm, s_red[i]);
            s_val = mm;
        }
        __syncthreads();
        float e = __expf(v - s_val);
        float s = e;
#pragma unroll
        for (int o = 16; o > 0; o >>= 1) s += __shfl_xor_sync(~0u, s, o);
        if (lane == 0) s_red[wid] = s;
        __syncthreads();
        if (tid == 0) {
            float ss = 0.0f;
#pragma unroll
            for (int i = 0; i < 8; i++) ss += s_red[i];
            s_val = ss;
        }
        __syncthreads();
        s_alpha[l][tid] = e / s_val;
        __syncthreads();
    }
    float acc[L][2];
#pragma unroll
    for (int l = 0; l < L; l++) { acc[l][0] = 0.0f; acc[l][1] = 0.0f; }
    const float* axb = att_x_em + (size_t)b * HW * H;
    for (int n = 0; n < HW; n++) {
        float2 ax = *(const float2*)&axb[(size_t)n * H + 2*tid];
#pragma unroll
        for (int l = 0; l < L; l++) {
            float a = s_alpha[l][n];
            acc[l][0] += a * ax.x;
            acc[l][1] += a * ax.y;
        }
    }
#pragma unroll
    for (int l = 0; l < L; l++) {
        __nv_bfloat162 ab2 = __floats2bfloat162_rn(acc[l][0], acc[l][1]);
        *(uint32_t*)&g_catbf[(size_t)(l*BATCH + b)*KCAT + 512 + 2*tid] = *(uint32_t*)&ab2;
    }
}

// ---------------- weight conversions to bf16 ----------------
__global__ void conv_lin_bf(const float* __restrict__ lin_w) {
    const size_t i = ((size_t)blockIdx.x * 256 + threadIdx.x) * 4;
    const size_t row = i / KCAT;
    float4 v = (row < NCLS) ? *(const float4*)&lin_w[i] : make_float4(0.f,0.f,0.f,0.f);
    __nv_bfloat162 a = __floats2bfloat162_rn(v.x, v.y);
    __nv_bfloat162 b = __floats2bfloat162_rn(v.z, v.w);
    *(uint2*)&g_linbf[i] = make_uint2(*(uint32_t*)&a, *(uint32_t*)&b);
}
__global__ void conv_f2bf(const float* __restrict__ src, __nv_bfloat16* __restrict__ dst) {
    const size_t i = ((size_t)blockIdx.x * 256 + threadIdx.x) * 4;
    float4 v = *(const float4*)&src[i];
    __nv_bfloat162 a = __floats2bfloat162_rn(v.x, v.y);
    __nv_bfloat162 b = __floats2bfloat162_rn(v.z, v.w);
    *(uint2*)&dst[i] = make_uint2(*(uint32_t*)&a, *(uint32_t*)&b);
}

// ---------------- K6: row log-softmax (vectorized float4) ----------------
__global__ void logsoftmax_kernel(float* __restrict__ out) {
    const int m = blockIdx.x;
    const int l = m / BATCH, b = m % BATCH;
    const int tid = threadIdx.x;
    const int lane = tid & 31, wid = tid >> 5;
    __shared__ float s_red[8];
    __shared__ float s_val;
    float4 vals[7];
    const float4* row = (const float4*)(g_logits + (size_t)m * NCLS);
#pragma unroll
    for (int i = 0; i < 7; i++) {
        int idx = tid + i*256;
        vals[i] = (idx < NCLS/4) ? row[idx] : make_float4(-1e30f,-1e30f,-1e30f,-1e30f);
    }
    float mx = -1e30f;
#pragma unroll
    for (int i = 0; i < 7; i++) {
        mx = fmaxf(mx, fmaxf(fmaxf(vals[i].x, vals[i].y), fmaxf(vals[i].z, vals[i].w)));
    }
#pragma unroll
    for (int o = 16; o > 0; o >>= 1) mx = fmaxf(mx, __shfl_xor_sync(~0u, mx, o));
    if (lane == 0) s_red[wid] = mx;
    __syncthreads();
    if (tid == 0) {
        float mm = s_red[0];
#pragma unroll
        for (int i = 1; i < 8; i++) mm = fmaxf(mm, s_red[i]);
        s_val = mm;
    }
    __syncthreads();
    const float mall = s_val;
    float sum = 0.0f;
#pragma unroll
    for (int i = 0; i < 7; i++) {
        sum += __expf(vals[i].x - mall) + __expf(vals[i].y - mall)
             + __expf(vals[i].z - mall) + __expf(vals[i].w - mall);
    }
#pragma unroll
    for (int o = 16; o > 0; o >>= 1) sum += __shfl_xor_sync(~0u, sum, o);
    if (lane == 0) s_red[wid] = sum;
    __syncthreads();
    if (tid == 0) {
        float ss = 0.0f;
#pragma unroll
        for (int i = 0; i < 8; i++) ss += s_red[i];
        s_val = ss;
    }
    __syncthreads();
    const float lse = mall + logf(s_val);
    float4* orow = (float4*)(out + ((size_t)b * L + l) * NCLS);
#pragma unroll
    for (int i = 0; i < 7; i++) {
        int idx = tid + i*256;
        if (idx < NCLS/4) {
            float4 v = vals[i];
            orow[idx] = make_float4(v.x - lse, v.y - lse, v.z - lse, v.w - lse);
        }
    }
}

// ---------------- launch ----------------
extern "C" void kernel_launch(void* const* d_in, const int* in_sizes, int n_in,
                              void* d_out, int out_size) {
    const float* hidden_en = (const float*)d_in[0];
    const float* x_em      = (const float*)d_in[1];
    const float* att_x_em  = (const float*)d_in[2];
    const int*   target    = (const int*)  d_in[3];
    const float* embed_w = (const float*)d_in[6];
    const float* W_ih    = (const float*)d_in[7];
    const float* W_hh    = (const float*)d_in[8];
    const float* b_ih    = (const float*)d_in[9];
    const float* b_hh    = (const float*)d_in[10];
    const float* hem_w   = (const float*)d_in[11];
    const float* hem_b   = (const float*)d_in[12];
    const float* attw_w  = (const float*)d_in[13];
    const float* attw_b  = (const float*)d_in[14];
    const float* lin_w   = (const float*)d_in[15];
    const float* lin_b   = (const float*)d_in[16];
    float* out = (float*)d_out;

    void *p_xg, *p_hem, *p_xtsbf, *p_catbf, *p_linbf, *p_whhbf, *p_wihbf, *p_hemwbf, *p_logits;
    cudaGetSymbolAddress(&p_xg,     g_xg);
    cudaGetSymbolAddress(&p_hem,    g_hem);
    cudaGetSymbolAddress(&p_xtsbf,  g_xtsbf);
    cudaGetSymbolAddress(&p_catbf,  g_catbf);
    cudaGetSymbolAddress(&p_linbf,  g_linbf);
    cudaGetSymbolAddress(&p_whhbf,  g_whhbf);
    cudaGetSymbolAddress(&p_wihbf,  g_wihbf);
    cudaGetSymbolAddress(&p_hemwbf, g_hemwbf);
    cudaGetSymbolAddress(&p_logits, g_logits);

    cudaFuncSetAttribute(lstm_persist, cudaFuncAttributeMaxDynamicSharedMemorySize, LP_SM_TOT);

    // K0 (bf16 out)
    gather_kernel<<<M5, 128>>>(hidden_en, embed_w, target);

    // weight conversions
    conv_lin_bf<<<(NPAD*KCAT/4)/256, 256>>>(lin_w);
    conv_f2bf<<<(G4*H/4)/256, 256>>>(W_hh, (__nv_bfloat16*)p_whhbf);
    conv_f2bf<<<(G4*HIDI/4)/256, 256>>>(W_ih, (__nv_bfloat16*)p_wihbf);
    conv_f2bf<<<(H*H/4)/256, 256>>>(hem_w, (__nv_bfloat16*)p_hemwbf);

    // K1: xg = xts @ W_ih^T + b_ih  (HMMA)
    hgemm_nt_bias<<<dim3(G4/128, M5/128), 256>>>(
        (const __nv_bfloat16*)p_xtsbf, HIDI, (const __nv_bfloat16*)p_wihbf, HIDI,
        b_ih, (float*)p_xg, G4, G4, HIDI);

    // K2: persistent LSTM (gate-sliced, 1 barrier/step)
    lstm_persist<<<LP_NBLK, 256, LP_SM_TOT>>>(b_hh);

    // K3: hem = h @ hem_w^T + hem_b  (HMMA)
    hgemm_nt_bias<<<dim3(H/128, M5/128), 256>>>(
        (const __nv_bfloat16*)p_catbf, KCAT, (const __nv_bfloat16*)p_hemwbf, H,
        hem_b, (float*)p_hem, H, H, H);

    // K4a, K4b
    featatt_kernel<<<dim3(16, BATCH), 256>>>(x_em, attw_w, attw_b);
    attred_kernel<<<BATCH, 256>>>(att_x_em);

    // K5: logits (HMMA)
    hgemm_nt_bias<<<dim3(NPAD/128, M5/128), 256>>>(
        (const __nv_bfloat16*)p_catbf, KCAT, (const __nv_bfloat16*)p_linbf, KCAT,
        lin_b, (float*)p_logits, NCLS, NCLS, KCAT);

    // K6
    logsoftmax_kernel<<<M5, 256>>>(out);
}

// round 8
// speedup vs baseline: 1.1253x; 1.1253x over previous
#include <cuda_runtime.h>
#include <cuda_bf16.h>
#include <math.h>
#include <cstdint>

#define L      40
#define BATCH  128
#define HIDI   512
#define H      512
#define G4     2048
#define NCLS   7000
#define NPAD   7040
#define HW     256
#define M5     (L*BATCH)   /* 5120 */
#define KCAT   1024

// ---------------- scratch (static device globals: no allocation) ----------------
__device__ float g_xg [M5*G4];
__device__ float g_hem[M5*H];
__device__ float g_fatt[M5*HW];
__device__ float g_c  [BATCH*H];
__device__ float g_part[4*BATCH*G4];             // LSTM k-split partials
__device__ float g_logits[(size_t)M5*NCLS];
__device__ __nv_bfloat16 g_xtsbf[M5*HIDI];
__device__ __nv_bfloat16 g_catbf[(size_t)M5*KCAT];   // h | att, bf16
__device__ __nv_bfloat16 g_linbf[(size_t)NPAD*KCAT];
__device__ __nv_bfloat16 g_whhbf[G4*H];
__device__ __nv_bfloat16 g_wihbf[G4*HIDI];
__device__ __nv_bfloat16 g_hemwbf[H*H];
__device__ unsigned int g_bar_cnt;
__device__ volatile unsigned int g_bar_gen;

__device__ __forceinline__ float tanh_approx(float x) {
    float y; asm("tanh.approx.f32 %0, %1;" : "=f"(y) : "f"(x)); return y;
}
__device__ __forceinline__ float sigmoid_acc(float x) { return 1.0f / (1.0f + expf(-x)); }

__device__ __forceinline__ uint32_t smem_u32(const void* p) {
    uint32_t a;
    asm("{ .reg .u64 t; cvta.to.shared.u64 t, %1; cvt.u32.u64 %0, t; }" : "=r"(a) : "l"(p));
    return a;
}
__device__ __forceinline__ void ldsm_x4(uint32_t* r, uint32_t addr) {
    asm volatile("ldmatrix.sync.aligned.m8n8.x4.shared.b16 {%0,%1,%2,%3}, [%4];"
                 : "=r"(r[0]), "=r"(r[1]), "=r"(r[2]), "=r"(r[3]) : "r"(addr));
}
__device__ __forceinline__ void mma16816(float* c, const uint32_t* a, uint32_t b0, uint32_t b1) {
    asm volatile("mma.sync.aligned.m16n8k16.row.col.f32.bf16.bf16.f32 "
                 "{%0,%1,%2,%3}, {%4,%5,%6,%7}, {%8,%9}, {%0,%1,%2,%3};"
                 : "+f"(c[0]), "+f"(c[1]), "+f"(c[2]), "+f"(c[3])
                 : "r"(a[0]), "r"(a[1]), "r"(a[2]), "r"(a[3]), "r"(b0), "r"(b1));
}

// grid-wide software barrier (all CTAs co-resident; count self-resets)
__device__ __forceinline__ void gbar(int nblk) {
    __syncthreads();
    if (threadIdx.x == 0) {
        __threadfence();
        unsigned int gen = g_bar_gen;
        if (atomicAdd(&g_bar_cnt, 1u) == (unsigned)(nblk - 1)) {
            g_bar_cnt = 0;
            __threadfence();
            g_bar_gen = gen + 1;
        } else {
            while (g_bar_gen == gen) { __nanosleep(32); }
        }
        __threadfence();
    }
    __syncthreads();
}

// ---------------- K0: gather teacher-forced inputs (bf16 out) ----------------
__global__ void gather_kernel(const float* __restrict__ hidden_en,
                              const float* __restrict__ embed_w,
                              const int*   __restrict__ target) {
    const int m = blockIdx.x;
    const int l = m / BATCH, b = m % BATCH;
    const int k = threadIdx.x * 4;
    const float* src = (l == 0)
        ? (hidden_en + (size_t)b * HIDI)
        : (embed_w   + (size_t)target[b * L + (l - 1)] * HIDI);
    float4 v = *(const float4*)&src[k];
    __nv_bfloat162 a = __floats2bfloat162_rn(v.x, v.y);
    __nv_bfloat162 c = __floats2bfloat162_rn(v.z, v.w);
    *(uint2*)&g_xtsbf[(size_t)m * HIDI + k] = make_uint2(*(uint32_t*)&a, *(uint32_t*)&c);
}

// ---------------- generic bf16 HMMA GEMM (K1, K3, K5) ----------------
#define HG_LDS   40
#define HG_ROWB  80
#define HG_BUFB  (128*HG_ROWB)

__global__ void __launch_bounds__(256) hgemm_nt_bias(
        const __nv_bfloat16* __restrict__ A, int lda,
        const __nv_bfloat16* __restrict__ B, int ldb,
        const float* __restrict__ bias,
        float* __restrict__ C, int ldc,
        int nlim, int K) {
    __shared__ __nv_bfloat16 sA[2][128][HG_LDS];
    __shared__ __nv_bfloat16 sB[2][128][HG_LDS];
    const int tid  = threadIdx.x;
    const int w    = tid >> 5, lane = tid & 31;
    const int wm   = w >> 2, wn = w & 3;
    const int bm   = blockIdx.y * 128;
    const int bn   = blockIdx.x * 128;
    const int nch  = K >> 5;

    const uint32_t uA = smem_u32(&sA[0][0][0]);
    const uint32_t uB = smem_u32(&sB[0][0][0]);

    const int gr0 = tid >> 1;
    const int gs0 = tid & 1;
    const int gs1 = 2 + (tid & 1);
    const __nv_bfloat16* arow = A + (size_t)(bm + gr0) * lda;
    const __nv_bfloat16* brow = B + (size_t)(bn + gr0) * ldb;

    float acc[4][4][4];
#pragma unroll
    for (int i = 0; i < 4; i++)
#pragma unroll
        for (int j = 0; j < 4; j++)
#pragma unroll
            for (int q = 0; q < 4; q++) acc[i][j][q] = 0.0f;

    uint4 ra[2], rb[2];
    ra[0] = *(const uint4*)(arow + gs0*8);
    ra[1] = *(const uint4*)(arow + gs1*8);
    rb[0] = *(const uint4*)(brow + gs0*8);
    rb[1] = *(const uint4*)(brow + gs1*8);
    *(uint4*)((char*)&sA[0][0][0] + gr0*HG_ROWB + gs0*16) = ra[0];
    *(uint4*)((char*)&sA[0][0][0] + gr0*HG_ROWB + gs1*16) = ra[1];
    *(uint4*)((char*)&sB[0][0][0] + gr0*HG_ROWB + gs0*16) = rb[0];
    *(uint4*)((char*)&sB[0][0][0] + gr0*HG_ROWB + gs1*16) = rb[1];

    const uint32_t aoff = (uint32_t)(wm*64 + (lane & 15)) * HG_ROWB + (uint32_t)(lane >> 4) * 16;
    const uint32_t boff = (uint32_t)(wn*32 + (lane & 15)) * HG_ROWB + (uint32_t)(lane >> 4) * 16;

    for (int c = 0; c < nch; c++) {
        __syncthreads();
        if (c + 1 < nch) {
            const int k0 = (c + 1) * 32;
            ra[0] = *(const uint4*)(arow + k0 + gs0*8);
            ra[1] = *(const uint4*)(arow + k0 + gs1*8);
            rb[0] = *(const uint4*)(brow + k0 + gs0*8);
            rb[1] = *(const uint4*)(brow + k0 + gs1*8);
        }
        const uint32_t bufA = uA + (c & 1) * HG_BUFB;
        const uint32_t bufB = uB + (c & 1) * HG_BUFB;
#pragma unroll
        for (int ka = 0; ka < 2; ka++) {
            uint32_t af[4][4];
            uint32_t bf[2][4];
#pragma unroll
            for (int ma = 0; ma < 4; ma++)
                ldsm_x4(af[ma], bufA + aoff + ma*16*HG_ROWB + ka*32);
#pragma unroll
            for (int ng = 0; ng < 2; ng++)
                ldsm_x4(bf[ng], bufB + boff + ng*16*HG_ROWB + ka*32);
#pragma unroll
            for (int ma = 0; ma < 4; ma++)
#pragma unroll
                for (int ng = 0; ng < 2; ng++) {
                    mma16816(acc[ma][ng*2+0], af[ma], bf[ng][0], bf[ng][2]);
                    mma16816(acc[ma][ng*2+1], af[ma], bf[ng][1], bf[ng][3]);
                }
        }
        if (c + 1 < nch) {
            __syncthreads();
            char* dA = (char*)&sA[(c+1)&1][0][0];
            char* dB = (char*)&sB[(c+1)&1][0][0];
            *(uint4*)(dA + gr0*HG_ROWB + gs0*16) = ra[0];
            *(uint4*)(dA + gr0*HG_ROWB + gs1*16) = ra[1];
            *(uint4*)(dB + gr0*HG_ROWB + gs0*16) = rb[0];
            *(uint4*)(dB + gr0*HG_ROWB + gs1*16) = rb[1];
        }
    }

    const int g = lane >> 2, t = lane & 3;
#pragma unroll
    for (int ma = 0; ma < 4; ma++) {
        const int r0 = bm + wm*64 + ma*16 + g;
#pragma unroll
        for (int na = 0; na < 4; na++) {
            const int col = bn + wn*32 + na*8 + t*2;
            if (col + 1 < nlim) {
                const float2 bv = *(const float2*)&bias[col];
                *(float2*)&C[(size_t)r0 * ldc + col] =
                    make_float2(acc[ma][na][0] + bv.x, acc[ma][na][1] + bv.y);
                *(float2*)&C[(size_t)(r0 + 8) * ldc + col] =
                    make_float2(acc[ma][na][2] + bv.x, acc[ma][na][3] + bv.y);
            }
        }
    }
}

// ---------------- persistent LSTM (R6 design: 128 CTAs, k-split 4, 2 gbars/step) ----------------
#define LP_NBLK 128
#define LP_ROWE 136
#define LP_ROWB 272

__global__ void __launch_bounds__(256) lstm_persist(const float* __restrict__ b_hh) {
    extern __shared__ __nv_bfloat16 sm[];
    __nv_bfloat16* sA = sm;
    __nv_bfloat16* sB = sm + 128*LP_ROWE;
    const int tid = threadIdx.x;
    const int w = tid >> 5, lane = tid & 31;
    const int wm = w >> 2, wn = w & 3;
    const int bid = blockIdx.x;
    const int bn = (bid & 31) * 64;
    const int ks = bid >> 5;
    const uint32_t uA = smem_u32(sA), uB = smem_u32(sB);
    const int g = lane >> 2, t4 = lane & 3;

    for (int i = tid; i < 64*16; i += 256) {
        int r = i >> 4, cc = i & 15;
        *(uint4*)((char*)sB + r*LP_ROWB + cc*16) =
            *(const uint4*)((const char*)(g_whhbf + (size_t)(bn + r)*H + ks*128) + cc*16);
    }

    const uint32_t aoff = uA + (uint32_t)(wm*64 + (lane & 15))*LP_ROWB + (uint32_t)(lane >> 4)*16;
    const uint32_t boff = uB + (uint32_t)(wn*16 + (lane & 15))*LP_ROWB + (uint32_t)(lane >> 4)*16;

    for (int l = 0; l < L; l++) {
        if (l > 0) {
            for (int i = tid; i < 128*16; i += 256) {
                int r = i >> 4, cc = i & 15;
                *(uint4*)((char*)sA + r*LP_ROWB + cc*16) =
                    *(const uint4*)((const char*)(g_catbf + (size_t)((l-1)*BATCH + r)*KCAT + ks*128) + cc*16);
            }
            __syncthreads();
            float acc[4][2][4];
#pragma unroll
            for (int ma = 0; ma < 4; ma++)
#pragma unroll
                for (int na = 0; na < 2; na++)
#pragma unroll
                    for (int q = 0; q < 4; q++) acc[ma][na][q] = 0.0f;
#pragma unroll
            for (int ka = 0; ka < 8; ka++) {
                uint32_t af[4][4], bfr[4];
#pragma unroll
                for (int ma = 0; ma < 4; ma++)
                    ldsm_x4(af[ma], aoff + ma*16*LP_ROWB + ka*32);
                ldsm_x4(bfr, boff + ka*32);
#pragma unroll
                for (int ma = 0; ma < 4; ma++) {
                    mma16816(acc[ma][0], af[ma], bfr[0], bfr[2]);
                    mma16816(acc[ma][1], af[ma], bfr[1], bfr[3]);
                }
            }
#pragma unroll
            for (int ma = 0; ma < 4; ma++) {
                const int r0 = wm*64 + ma*16 + g;
#pragma unroll
                for (int na = 0; na < 2; na++) {
                    const int col = bn + wn*16 + na*8 + t4*2;
                    *(float2*)&g_part[((size_t)ks*BATCH + r0)*G4 + col] =
                        make_float2(acc[ma][na][0], acc[ma][na][1]);
                    *(float2*)&g_part[((size_t)ks*BATCH + r0 + 8)*G4 + col] =
                        make_float2(acc[ma][na][2], acc[ma][na][3]);
                }
            }
            gbar(LP_NBLK);
        }
        {
            const int e0 = bid*512 + tid*2;
            const int b = e0 >> 9, d = e0 & 511;
            float2 gv[4];
#pragma unroll
            for (int q = 0; q < 4; q++) {
                const int n = q*H + d;
                float2 v = *(const float2*)&g_xg[(size_t)(l*BATCH + b)*G4 + n];
                v.x += b_hh[n]; v.y += b_hh[n+1];
                if (l > 0) {
#pragma unroll
                    for (int s = 0; s < 4; s++) {
                        float2 p = *(const float2*)&g_part[((size_t)s*BATCH + b)*G4 + n];
                        v.x += p.x; v.y += p.y;
                    }
                }
                gv[q] = v;
            }
            float2 cp = make_float2(0.f, 0.f);
            if (l > 0) cp = *(const float2*)&g_c[b*H + d];
            float hx, hy;
            {
                float ig = sigmoid_acc(gv[0].x), fg = sigmoid_acc(gv[1].x);
                float gg = tanhf(gv[2].x),       og = sigmoid_acc(gv[3].x);
                float cn = fg*cp.x + ig*gg;
                cp.x = cn; hx = og * tanhf(cn);
            }
            {
                float ig = sigmoid_acc(gv[0].y), fg = sigmoid_acc(gv[1].y);
                float gg = tanhf(gv[2].y),       og = sigmoid_acc(gv[3].y);
                float cn = fg*cp.y + ig*gg;
                cp.y = cn; hy = og * tanhf(cn);
            }
            *(float2*)&g_c[b*H + d] = cp;
            __nv_bfloat162 hb = __floats2bfloat162_rn(hx, hy);
            *(uint32_t*)&g_catbf[(size_t)(l*BATCH + b)*KCAT + d] = *(uint32_t*)&hb;
        }
        gbar(LP_NBLK);
    }
}

// ---------------- K4a ----------------
__global__ void featatt_kernel(const float* __restrict__ x_em,
                               const float* __restrict__ attw_w,
                               const float* __restrict__ attw_b) {
    __shared__ float sx[512][17];
    __shared__ float sh_hem[512];
    __shared__ float sh_w[512];
    __shared__ float red[16][17];
    const int tid = threadIdx.x;
    const int b  = blockIdx.y;
    const int n0 = blockIdx.x * 16;
#pragma unroll
    for (int i = 0; i < 32; i++) {
        int e = tid + i*256;
        int c = e >> 4, j = e & 15;
        sx[c][j] = x_em[((size_t)b*512 + c) * 256 + n0 + j];
    }
    sh_w[tid]     = attw_w[tid];
    sh_w[tid+256] = attw_w[tid+256];
    const float ab = attw_b[0];
    const int j  = tid % 16;
    const int cg = tid / 16;
    for (int l = 0; l < L; l++) {
        __syncthreads();
        sh_hem[tid]     = g_hem[(size_t)(l*BATCH + b) * H + tid];
        sh_hem[tid+256] = g_hem[(size_t)(l*BATCH + b) * H + tid + 256];
        __syncthreads();
        float acc = 0.0f;
#pragma unroll 8
        for (int i = 0; i < 32; i++) {
            int c = cg*32 + i;
            acc += tanh_approx(sx[c][j] + sh_hem[c]) * sh_w[c];
        }
        red[cg][j] = acc;
        __syncthreads();
        if (tid < 16) {
            float s = 0.0f;
#pragma unroll
            for (int i = 0; i < 16; i++) s += red[i][tid];
            g_fatt[(size_t)(l*BATCH + b) * HW + n0 + tid] = s + ab;
        }
    }
}

// ---------------- K4b ----------------
__global__ void attred_kernel(const float* __restrict__ att_x_em) {
    __shared__ float s_alpha[L][HW];
    __shared__ float s_red[8];
    __shared__ float s_val;
    const int tid = threadIdx.x;
    const int b = blockIdx.x;
    const int lane = tid & 31, wid = tid >> 5;
    for (int l = 0; l < L; l++) {
        float v = g_fatt[(size_t)(l*BATCH + b) * HW + tid];
        float m = v;
#pragma unroll
        for (int o = 16; o > 0; o >>= 1) m = fmaxf(m, __shfl_xor_sync(~0u, m, o));
        if (lane == 0) s_red[wid] = m;
        __syncthreads();
        if (tid == 0) {
            float mm = s_red[0];
#pragma unroll
            for (int i = 1; i < 8; i++) mm = fmaxf(mm, s_red[i]);
            s_val = mm;
        }
        __syncthreads();
        float e = __expf(v - s_val);
        float s = e;
#pragma unroll
        for (int o = 16; o > 0; o >>= 1) s += __shfl_xor_sync(~0u, s, o);
        if (lane == 0) s_red[wid] = s;
        __syncthreads();
        if (tid == 0) {
            float ss = 0.0f;
#pragma unroll
            for (int i = 0; i < 8; i++) ss += s_red[i];
            s_val = ss;
        }
        __syncthreads();
        s_alpha[l][tid] = e / s_val;
        __syncthreads();
    }
    float acc[L][2];
#pragma unroll
    for (int l = 0; l < L; l++) { acc[l][0] = 0.0f; acc[l][1] = 0.0f; }
    const float* axb = att_x_em + (size_t)b * HW * H;
    for (int n = 0; n < HW; n++) {
        float2 ax = *(const float2*)&axb[(size_t)n * H + 2*tid];
#pragma unroll
        for (int l = 0; l < L; l++) {
            float a = s_alpha[l][n];
            acc[l][0] += a * ax.x;
            acc[l][1] += a * ax.y;
        }
    }
#pragma unroll
    for (int l = 0; l < L; l++) {
        __nv_bfloat162 ab2 = __floats2bfloat162_rn(acc[l][0], acc[l][1]);
        *(uint32_t*)&g_catbf[(size_t)(l*BATCH + b)*KCAT + 512 + 2*tid] = *(uint32_t*)&ab2;
    }
}

// ---------------- weight conversions to bf16 ----------------
__global__ void conv_lin_bf(const float* __restrict__ lin_w) {
    const size_t i = ((size_t)blockIdx.x * 256 + threadIdx.x) * 4;
    const size_t row = i / KCAT;
    float4 v = (row < NCLS) ? *(const float4*)&lin_w[i] : make_float4(0.f,0.f,0.f,0.f);
    __nv_bfloat162 a = __floats2bfloat162_rn(v.x, v.y);
    __nv_bfloat162 b = __floats2bfloat162_rn(v.z, v.w);
    *(uint2*)&g_linbf[i] = make_uint2(*(uint32_t*)&a, *(uint32_t*)&b);
}
__global__ void conv_f2bf(const float* __restrict__ src, __nv_bfloat16* __restrict__ dst) {
    const size_t i = ((size_t)blockIdx.x * 256 + threadIdx.x) * 4;
    float4 v = *(const float4*)&src[i];
    __nv_bfloat162 a = __floats2bfloat162_rn(v.x, v.y);
    __nv_bfloat162 b = __floats2bfloat162_rn(v.z, v.w);
    *(uint2*)&dst[i] = make_uint2(*(uint32_t*)&a, *(uint32_t*)&b);
}

// ---------------- K6: row log-softmax (vectorized float4) ----------------
__global__ void logsoftmax_kernel(float* __restrict__ out) {
    const int m = blockIdx.x;
    const int l = m / BATCH, b = m % BATCH;
    const int tid = threadIdx.x;
    const int lane = tid & 31, wid = tid >> 5;
    __shared__ float s_red[8];
    __shared__ float s_val;
    float4 vals[7];
    const float4* row = (const float4*)(g_logits + (size_t)m * NCLS);
#pragma unroll
    for (int i = 0; i < 7; i++) {
        int idx = tid + i*256;
        vals[i] = (idx < NCLS/4) ? row[idx] : make_float4(-1e30f,-1e30f,-1e30f,-1e30f);
    }
    float mx = -1e30f;
#pragma unroll
    for (int i = 0; i < 7; i++) {
        mx = fmaxf(mx, fmaxf(fmaxf(vals[i].x, vals[i].y), fmaxf(vals[i].z, vals[i].w)));
    }
#pragma unroll
    for (int o = 16; o > 0; o >>= 1) mx = fmaxf(mx, __shfl_xor_sync(~0u, mx, o));
    if (lane == 0) s_red[wid] = mx;
    __syncthreads();
    if (tid == 0) {
        float mm = s_red[0];
#pragma unroll
        for (int i = 1; i < 8; i++) mm = fmaxf(mm, s_red[i]);
        s_val = mm;
    }
    __syncthreads();
    const float mall = s_val;
    float sum = 0.0f;
#pragma unroll
    for (int i = 0; i < 7; i++) {
        sum += __expf(vals[i].x - mall) + __expf(vals[i].y - mall)
             + __expf(vals[i].z - mall) + __expf(vals[i].w - mall);
    }
#pragma unroll
    for (int o = 16; o > 0; o >>= 1) sum += __shfl_xor_sync(~0u, sum, o);
    if (lane == 0) s_red[wid] = sum;
    __syncthreads();
    if (tid == 0) {
        float ss = 0.0f;
#pragma unroll
        for (int i = 0; i < 8; i++) ss += s_red[i];
        s_val = ss;
    }
    __syncthreads();
    const float lse = mall + logf(s_val);
    float4* orow = (float4*)(out + ((size_t)b * L + l) * NCLS);
#pragma unroll
    for (int i = 0; i < 7; i++) {
        int idx = tid + i*256;
        if (idx < NCLS/4) {
            float4 v = vals[i];
            orow[idx] = make_float4(v.x - lse, v.y - lse, v.z - lse, v.w - lse);
        }
    }
}

// ---------------- launch ----------------
extern "C" void kernel_launch(void* const* d_in, const int* in_sizes, int n_in,
                              void* d_out, int out_size) {
    const float* hidden_en = (const float*)d_in[0];
    const float* x_em      = (const float*)d_in[1];
    const float* att_x_em  = (const float*)d_in[2];
    const int*   target    = (const int*)  d_in[3];
    const float* embed_w = (const float*)d_in[6];
    const float* W_ih    = (const float*)d_in[7];
    const float* W_hh    = (const float*)d_in[8];
    const float* b_ih    = (const float*)d_in[9];
    const float* b_hh    = (const float*)d_in[10];
    const float* hem_w   = (const float*)d_in[11];
    const float* hem_b   = (const float*)d_in[12];
    const float* attw_w  = (const float*)d_in[13];
    const float* attw_b  = (const float*)d_in[14];
    const float* lin_w   = (const float*)d_in[15];
    const float* lin_b   = (const float*)d_in[16];
    float* out = (float*)d_out;

    void *p_xg, *p_hem, *p_xtsbf, *p_catbf, *p_linbf, *p_whhbf, *p_wihbf, *p_hemwbf, *p_logits;
    cudaGetSymbolAddress(&p_xg,     g_xg);
    cudaGetSymbolAddress(&p_hem,    g_hem);
    cudaGetSymbolAddress(&p_xtsbf,  g_xtsbf);
    cudaGetSymbolAddress(&p_catbf,  g_catbf);
    cudaGetSymbolAddress(&p_linbf,  g_linbf);
    cudaGetSymbolAddress(&p_whhbf,  g_whhbf);
    cudaGetSymbolAddress(&p_wihbf,  g_wihbf);
    cudaGetSymbolAddress(&p_hemwbf, g_hemwbf);
    cudaGetSymbolAddress(&p_logits, g_logits);

    const int lp_smem = (128 + 64) * LP_ROWE * 2;
    cudaFuncSetAttribute(lstm_persist, cudaFuncAttributeMaxDynamicSharedMemorySize, lp_smem);

    // K0 (bf16 out)
    gather_kernel<<<M5, 128>>>(hidden_en, embed_w, target);

    // weight conversions
    conv_lin_bf<<<(NPAD*KCAT/4)/256, 256>>>(lin_w);
    conv_f2bf<<<(G4*H/4)/256, 256>>>(W_hh, (__nv_bfloat16*)p_whhbf);
    conv_f2bf<<<(G4*HIDI/4)/256, 256>>>(W_ih, (__nv_bfloat16*)p_wihbf);
    conv_f2bf<<<(H*H/4)/256, 256>>>(hem_w, (__nv_bfloat16*)p_hemwbf);

    // K1: xg = xts @ W_ih^T + b_ih  (HMMA)
    hgemm_nt_bias<<<dim3(G4/128, M5/128), 256>>>(
        (const __nv_bfloat16*)p_xtsbf, HIDI, (const __nv_bfloat16*)p_wihbf, HIDI,
        b_ih, (float*)p_xg, G4, G4, HIDI);

    // K2: persistent LSTM (R6 design)
    lstm_persist<<<LP_NBLK, 256, lp_smem>>>(b_hh);

    // K3: hem = h @ hem_w^T + hem_b  (HMMA)
    hgemm_nt_bias<<<dim3(H/128, M5/128), 256>>>(
        (const __nv_bfloat16*)p_catbf, KCAT, (const __nv_bfloat16*)p_hemwbf, H,
        hem_b, (float*)p_hem, H, H, H);

    // K4a, K4b
    featatt_kernel<<<dim3(16, BATCH), 256>>>(x_em, attw_w, attw_b);
    attred_kernel<<<BATCH, 256>>>(att_x_em);

    // K5: logits (HMMA)
    hgemm_nt_bias<<<dim3(NPAD/128, M5/128), 256>>>(
        (const __nv_bfloat16*)p_catbf, KCAT, (const __nv_bfloat16*)p_linbf, KCAT,
        lin_b, (float*)p_logits, NCLS, NCLS, KCAT);

    // K6
    logsoftmax_kernel<<<M5, 256>>>(out);
}